// round 8
// baseline (speedup 1.0000x reference)
#include <cuda_runtime.h>
#include <cuda_bf16.h>
#include <cstdint>

#define EMB_D    256
#define BATCH    128
#define NC       10000
#define NTILE    40                     // tails per tile; 250 * 40 = 10000
#define BHALF    64                     // batch rows per CTA
#define NBLK_S   500                    // 250 n-tiles x 2 batch halves
#define NTHREADS 128                    // 4 warps

// smem: left 64 rows x 512B = 32768 B (words 0..8191), t 40 x 512B = 20480 B
#define OFF_TS_W 8192                   // word offset of t tile
#define SMEM_DYN 53248

// device-global scratch
__device__ __align__(16) uint4 g_leftT[BATCH * 32];
__device__ float g_ln[BATCH];
__device__ __align__(16) uint4 g_tT[NC * 32];
__device__ float g_tn[NC];

// ---------------------------------------------------------------------------
__device__ __forceinline__ void mma_bf16(float* c,
                                         uint32_t a0, uint32_t a1, uint32_t a2, uint32_t a3,
                                         uint32_t b0, uint32_t b1) {
    asm volatile(
        "mma.sync.aligned.m16n8k16.row.col.f32.bf16.bf16.f32 "
        "{%0,%1,%2,%3}, {%4,%5,%6,%7}, {%8,%9}, {%0,%1,%2,%3};"
        : "+f"(c[0]), "+f"(c[1]), "+f"(c[2]), "+f"(c[3])
        : "r"(a0), "r"(a1), "r"(a2), "r"(a3), "r"(b0), "r"(b1));
}

__device__ __forceinline__ uint32_t pack_bf16x2(float lo, float hi) {
    __nv_bfloat162 p = __floats2bfloat162_rn(lo, hi);
    return *reinterpret_cast<uint32_t*>(&p);
}

__device__ __forceinline__ float warp_sum(float s) {
    #pragma unroll
    for (int o = 16; o; o >>= 1) s += __shfl_xor_sync(0xffffffffu, s, o);
    return s;
}

__device__ __forceinline__ void cp_async16(uint32_t smem_dst, const void* gsrc) {
    asm volatile("cp.async.ca.shared.global [%0], [%1], 16;"
                 :: "r"(smem_dst), "l"(gsrc) : "memory");
}

__device__ __forceinline__ uint32_t cvta_smem(const void* p) {
    uint32_t a;
    asm("{ .reg .u64 t; cvta.to.shared.u64 t, %1; cvt.u32.u64 %0, t; }"
        : "=r"(a) : "l"(p));
    return a;
}

// ---------------------------------------------------------------------------
// Kernel 1: pack dense bf16 candidate matrix + norms (2 rows per warp,
// 625 CTAs); CTAs 0..15 also build left = ent[heads]+rel[rels].
// ---------------------------------------------------------------------------
__global__ void __launch_bounds__(256)
pack_kernel(const float* __restrict__ ent, const float* __restrict__ rel,
            const int* __restrict__ heads, const int* __restrict__ rels,
            const int* __restrict__ tails) {
    const int wid  = threadIdx.x >> 5;
    const int lane = threadIdx.x & 31;

    // ---- pack 2 tail rows per warp ----
    {
        const int nb = blockIdx.x * 16 + wid * 2;
        int i0 = tails[nb], i1 = tails[nb + 1];
        const float4* s0 = reinterpret_cast<const float4*>(ent + (size_t)i0 * EMB_D);
        const float4* s1 = reinterpret_cast<const float4*>(ent + (size_t)i1 * EMB_D);
        float4 a0 = s0[lane * 2], b0 = s0[lane * 2 + 1];
        float4 a1 = s1[lane * 2], b1 = s1[lane * 2 + 1];

        float n0 = a0.x*a0.x + a0.y*a0.y + a0.z*a0.z + a0.w*a0.w
                 + b0.x*b0.x + b0.y*b0.y + b0.z*b0.z + b0.w*b0.w;
        float n1 = a1.x*a1.x + a1.y*a1.y + a1.z*a1.z + a1.w*a1.w
                 + b1.x*b1.x + b1.y*b1.y + b1.z*b1.z + b1.w*b1.w;
        n0 = warp_sum(n0);
        n1 = warp_sum(n1);
        if (lane == 0) { g_tn[nb] = n0; g_tn[nb + 1] = n1; }

        uint4 p0, p1;
        p0.x = pack_bf16x2(a0.x, a0.y); p0.y = pack_bf16x2(a0.z, a0.w);
        p0.z = pack_bf16x2(b0.x, b0.y); p0.w = pack_bf16x2(b0.z, b0.w);
        p1.x = pack_bf16x2(a1.x, a1.y); p1.y = pack_bf16x2(a1.z, a1.w);
        p1.z = pack_bf16x2(b1.x, b1.y); p1.w = pack_bf16x2(b1.z, b1.w);
        g_tT[(size_t)nb * 32 + lane]       = p0;
        g_tT[(size_t)(nb + 1) * 32 + lane] = p1;
    }

    // ---- CTAs 0..15: build left rows (one per warp) ----
    if (blockIdx.x < 16) {
        const int r  = blockIdx.x * 8 + wid;
        const int h  = heads[r];
        const int rl = rels[r];
        const float4* eh = reinterpret_cast<const float4*>(ent + (size_t)h * EMB_D);
        const float4* rr = reinterpret_cast<const float4*>(rel + (size_t)rl * EMB_D);
        float4 a0 = eh[lane * 2], a1 = eh[lane * 2 + 1];
        float4 b0 = rr[lane * 2], b1 = rr[lane * 2 + 1];
        float v0 = a0.x + b0.x, v1 = a0.y + b0.y, v2 = a0.z + b0.z, v3 = a0.w + b0.w;
        float v4 = a1.x + b1.x, v5 = a1.y + b1.y, v6 = a1.z + b1.z, v7 = a1.w + b1.w;
        float s = v0*v0 + v1*v1 + v2*v2 + v3*v3 + v4*v4 + v5*v5 + v6*v6 + v7*v7;
        s = warp_sum(s);
        if (lane == 0) g_ln[r] = s;
        uint4 pk;
        pk.x = pack_bf16x2(v0, v1);
        pk.y = pack_bf16x2(v2, v3);
        pk.z = pack_bf16x2(v4, v5);
        pk.w = pack_bf16x2(v6, v7);
        g_leftT[r * 32 + lane] = pk;
    }
}

// ---------------------------------------------------------------------------
// Kernel 2: score. Tile = 64 batch x 40 tails, 4 warps (m-split 4x16, all
// warps share the 40 n-columns), XOR-swizzled smem (52KB), grid 500.
// ---------------------------------------------------------------------------
__global__ void __launch_bounds__(NTHREADS, 4)
score_kernel(float* __restrict__ out) {
    extern __shared__ __align__(16) char smem[];
    uint32_t* lS = reinterpret_cast<uint32_t*>(smem);
    uint32_t* tS = lS + OFF_TS_W;
    const uint32_t lS_a = cvta_smem(lS);
    const uint32_t tS_a = cvta_smem(tS);

    const int tid  = threadIdx.x;
    const int wid  = tid >> 5;
    const int lane = tid & 31;
    const int n0   = (blockIdx.x >> 1) * NTILE;
    const int half = blockIdx.x & 1;

    // ---- stage left half (64 rows, 2048 uint4) with XOR swizzle ----
    #pragma unroll
    for (int it = 0; it < 16; it++) {
        const int i   = it * NTHREADS + tid;
        const int row = i >> 5;
        const int u   = i & 31;
        const uint32_t w = (uint32_t)(row * 128 + ((u ^ (row & 7)) << 2));
        cp_async16(lS_a + w * 4u, &g_leftT[(half * BHALF + row) * 32 + u]);
    }
    // ---- stage t (40 rows, 1280 uint4) ----
    #pragma unroll
    for (int it = 0; it < 10; it++) {
        const int i   = it * NTHREADS + tid;
        const int row = i >> 5;
        const int u   = i & 31;
        const uint32_t w = (uint32_t)(row * 128 + ((u ^ (row & 7)) << 2));
        cp_async16(tS_a + w * 4u, &g_tT[(size_t)(n0 + row) * 32 + u]);
    }
    asm volatile("cp.async.commit_group;" ::: "memory");

    // ---- norms into registers (L2-hot, overlaps cp.async) ----
    const int m0  = wid * 16;
    const int g   = lane >> 2;
    const int tig = lane & 3;

    const int bgl = half * BHALF + m0 + g;
    const float l0 = g_ln[bgl];
    const float l1 = g_ln[bgl + 8];
    float t0r[5], t1r[5];
    #pragma unroll
    for (int nb = 0; nb < 5; nb++) {
        const int col = nb * 8 + tig * 2;
        t0r[nb] = g_tn[n0 + col];
        t1r[nb] = g_tn[n0 + col + 1];
    }

    asm volatile("cp.async.wait_group 0;" ::: "memory");
    __syncthreads();

    // ---- HMMA mainloop: warp tile 16(batch) x 40(tails) ----
    float acc[5][4];
    #pragma unroll
    for (int nb = 0; nb < 5; nb++)
        #pragma unroll
        for (int c = 0; c < 4; c++) acc[nb][c] = 0.0f;

    const int baseA = (m0 + g) * 128 + tig;
    int baseB[5];
    #pragma unroll
    for (int nb = 0; nb < 5; nb++) baseB[nb] = (nb * 8 + g) * 128 + tig;

    #pragma unroll 4
    for (int ks = 0; ks < 16; ks++) {
        const int e0 = (2 * ks) ^ g;
        const int o0 = e0 << 2;
        const int o1 = (e0 ^ 1) << 2;

        uint32_t a0 = lS[baseA + o0];
        uint32_t a1 = lS[baseA + 1024 + o0];
        uint32_t a2 = lS[baseA + o1];
        uint32_t a3 = lS[baseA + 1024 + o1];

        uint32_t bb[5][2];
        #pragma unroll
        for (int nb = 0; nb < 5; nb++) {
            bb[nb][0] = tS[baseB[nb] + o0];
            bb[nb][1] = tS[baseB[nb] + o1];
        }
        #pragma unroll
        for (int nb = 0; nb < 5; nb++)
            mma_bf16(acc[nb], a0, a1, a2, a3, bb[nb][0], bb[nb][1]);
    }

    // ---- epilogue ----
    #pragma unroll
    for (int nb = 0; nb < 5; nb++) {
        const int n = n0 + nb * 8 + tig * 2;
        float v, sq;
        float2 w0, w1;
        v = fmaxf(l0 + t0r[nb] - 2.0f * acc[nb][0], 0.0f);
        asm("sqrt.approx.f32 %0, %1;" : "=f"(sq) : "f"(v));  w0.x = -sq;
        v = fmaxf(l0 + t1r[nb] - 2.0f * acc[nb][1], 0.0f);
        asm("sqrt.approx.f32 %0, %1;" : "=f"(sq) : "f"(v));  w0.y = -sq;
        v = fmaxf(l1 + t0r[nb] - 2.0f * acc[nb][2], 0.0f);
        asm("sqrt.approx.f32 %0, %1;" : "=f"(sq) : "f"(v));  w1.x = -sq;
        v = fmaxf(l1 + t1r[nb] - 2.0f * acc[nb][3], 0.0f);
        asm("sqrt.approx.f32 %0, %1;" : "=f"(sq) : "f"(v));  w1.y = -sq;

        *reinterpret_cast<float2*>(out + (size_t)bgl * NC + n)       = w0;
        *reinterpret_cast<float2*>(out + (size_t)(bgl + 8) * NC + n) = w1;
    }
}

// ---------------------------------------------------------------------------
extern "C" void kernel_launch(void* const* d_in, const int* in_sizes, int n_in,
                              void* d_out, int out_size) {
    const float* ent   = (const float*)d_in[0];
    const float* rel   = (const float*)d_in[1];
    const int*   heads = (const int*)d_in[2];
    const int*   rels  = (const int*)d_in[3];
    const int*   tails = (const int*)d_in[4];
    float* out = (float*)d_out;

    cudaFuncSetAttribute(score_kernel,
                         cudaFuncAttributeMaxDynamicSharedMemorySize, SMEM_DYN);

    pack_kernel<<<NC / 16, 256>>>(ent, rel, heads, rels, tails);
    score_kernel<<<NBLK_S, NTHREADS, SMEM_DYN>>>(out);
}

// round 9
// speedup vs baseline: 1.1376x; 1.1376x over previous
#include <cuda_runtime.h>
#include <cuda_bf16.h>
#include <cstdint>

#define EMB_D    256
#define BATCH    128
#define NC       10000
#define NTILE    40                     // 250 * 40 = 10000
#define NBLK_S   250
#define NTHREADS 256                    // 8 warps

// smem: left 128 rows x 512B = 65536, t 40 rows x 512B = 20480
#define OFF_TS_B 65536
#define SMEM_DYN 86016

// device-global scratch
__device__ __align__(16) uint4 g_leftT[BATCH * 32];
__device__ float g_ln[BATCH];
__device__ __align__(16) uint4 g_tT[NC * 32];
__device__ float g_tn[NC];

// ---------------------------------------------------------------------------
__device__ __forceinline__ void mma_bf16(float* c,
                                         uint32_t a0, uint32_t a1, uint32_t a2, uint32_t a3,
                                         uint32_t b0, uint32_t b1) {
    asm volatile(
        "mma.sync.aligned.m16n8k16.row.col.f32.bf16.bf16.f32 "
        "{%0,%1,%2,%3}, {%4,%5,%6,%7}, {%8,%9}, {%0,%1,%2,%3};"
        : "+f"(c[0]), "+f"(c[1]), "+f"(c[2]), "+f"(c[3])
        : "r"(a0), "r"(a1), "r"(a2), "r"(a3), "r"(b0), "r"(b1));
}

__device__ __forceinline__ void ldsm_x4(uint32_t& r0, uint32_t& r1,
                                        uint32_t& r2, uint32_t& r3, uint32_t addr) {
    asm volatile("ldmatrix.sync.aligned.m8n8.x4.shared.b16 {%0,%1,%2,%3}, [%4];"
                 : "=r"(r0), "=r"(r1), "=r"(r2), "=r"(r3) : "r"(addr));
}

__device__ __forceinline__ void ldsm_x2(uint32_t& r0, uint32_t& r1, uint32_t addr) {
    asm volatile("ldmatrix.sync.aligned.m8n8.x2.shared.b16 {%0,%1}, [%2];"
                 : "=r"(r0), "=r"(r1) : "r"(addr));
}

__device__ __forceinline__ uint32_t pack_bf16x2(float lo, float hi) {
    __nv_bfloat162 p = __floats2bfloat162_rn(lo, hi);
    return *reinterpret_cast<uint32_t*>(&p);
}

__device__ __forceinline__ float warp_sum(float s) {
    #pragma unroll
    for (int o = 16; o; o >>= 1) s += __shfl_xor_sync(0xffffffffu, s, o);
    return s;
}

__device__ __forceinline__ void cp_async16(uint32_t smem_dst, const void* gsrc) {
    asm volatile("cp.async.cg.shared.global [%0], [%1], 16;"
                 :: "r"(smem_dst), "l"(gsrc) : "memory");
}

__device__ __forceinline__ uint32_t cvta_smem(const void* p) {
    uint32_t a;
    asm("{ .reg .u64 t; cvta.to.shared.u64 t, %1; cvt.u32.u64 %0, t; }"
        : "=r"(a) : "l"(p));
    return a;
}

// ---------------------------------------------------------------------------
// Kernel 1: pack dense bf16 candidate matrix + norms. 8 warps x 4 rows = 32
// rows/CTA, grid 313 (high gather MLP). CTAs 0..15 also build left.
// ---------------------------------------------------------------------------
__global__ void __launch_bounds__(256)
pack_kernel(const float* __restrict__ ent, const float* __restrict__ rel,
            const int* __restrict__ heads, const int* __restrict__ rels,
            const int* __restrict__ tails) {
    const int wid  = threadIdx.x >> 5;
    const int lane = threadIdx.x & 31;

    {
        const int nb = blockIdx.x * 32 + wid * 4;
        int idx[4];
        #pragma unroll
        for (int u = 0; u < 4; u++) {
            int n = nb + u;
            idx[u] = tails[n < NC ? n : NC - 1];
        }
        float4 va[4], vb[4];
        #pragma unroll
        for (int u = 0; u < 4; u++) {
            const float4* src = reinterpret_cast<const float4*>(ent + (size_t)idx[u] * EMB_D);
            va[u] = src[lane * 2];
            vb[u] = src[lane * 2 + 1];
        }
        #pragma unroll
        for (int u = 0; u < 4; u++) {
            const int n = nb + u;
            float s = va[u].x*va[u].x + va[u].y*va[u].y + va[u].z*va[u].z + va[u].w*va[u].w
                    + vb[u].x*vb[u].x + vb[u].y*vb[u].y + vb[u].z*vb[u].z + vb[u].w*vb[u].w;
            s = warp_sum(s);
            if (n < NC) {
                if (lane == 0) g_tn[n] = s;
                uint4 pk;
                pk.x = pack_bf16x2(va[u].x, va[u].y);
                pk.y = pack_bf16x2(va[u].z, va[u].w);
                pk.z = pack_bf16x2(vb[u].x, vb[u].y);
                pk.w = pack_bf16x2(vb[u].z, vb[u].w);
                g_tT[(size_t)n * 32 + lane] = pk;
            }
        }
    }

    if (blockIdx.x < 16) {
        const int r  = blockIdx.x * 8 + wid;
        const int h  = heads[r];
        const int rl = rels[r];
        const float4* eh = reinterpret_cast<const float4*>(ent + (size_t)h * EMB_D);
        const float4* rr = reinterpret_cast<const float4*>(rel + (size_t)rl * EMB_D);
        float4 a0 = eh[lane * 2], a1 = eh[lane * 2 + 1];
        float4 b0 = rr[lane * 2], b1 = rr[lane * 2 + 1];
        float v0 = a0.x + b0.x, v1 = a0.y + b0.y, v2 = a0.z + b0.z, v3 = a0.w + b0.w;
        float v4 = a1.x + b1.x, v5 = a1.y + b1.y, v6 = a1.z + b1.z, v7 = a1.w + b1.w;
        float s = v0*v0 + v1*v1 + v2*v2 + v3*v3 + v4*v4 + v5*v5 + v6*v6 + v7*v7;
        s = warp_sum(s);
        if (lane == 0) g_ln[r] = s;
        uint4 pk;
        pk.x = pack_bf16x2(v0, v1);
        pk.y = pack_bf16x2(v2, v3);
        pk.z = pack_bf16x2(v4, v5);
        pk.w = pack_bf16x2(v6, v7);
        g_leftT[r * 32 + lane] = pk;
    }
}

// ---------------------------------------------------------------------------
// Kernel 2: score. Tile = 128 batch x 40 tails, 8 warps m-split, split-K
// cp.async (2 groups), ldmatrix fragment loads, XOR-swizzled smem.
// ---------------------------------------------------------------------------
__global__ void __launch_bounds__(NTHREADS, 2)
score_kernel(float* __restrict__ out) {
    extern __shared__ __align__(16) char smem[];
    const uint32_t lS_a = cvta_smem(smem);
    const uint32_t tS_a = lS_a + OFF_TS_B;

    const int tid  = threadIdx.x;
    const int wid  = tid >> 5;
    const int lane = tid & 31;
    const int n0   = blockIdx.x * NTILE;

    // ---- group 0: k chunks 0..15 (k = 0..127) ----
    #pragma unroll
    for (int it = 0; it < 8; it++) {                  // left: 128 rows x 16 ch
        const int i = it * NTHREADS + tid;
        const int row = i >> 4, u = i & 15;
        cp_async16(lS_a + (uint32_t)(row * 512 + ((u ^ (row & 7)) << 4)),
                   &g_leftT[row * 32 + u]);
    }
    #pragma unroll
    for (int it = 0; it < 3; it++) {                  // t: 40 rows x 16 ch = 640
        const int i = it * NTHREADS + tid;
        if (i < 640) {
            const int row = i >> 4, u = i & 15;
            cp_async16(tS_a + (uint32_t)(row * 512 + ((u ^ (row & 7)) << 4)),
                       &g_tT[(size_t)(n0 + row) * 32 + u]);
        }
    }
    asm volatile("cp.async.commit_group;" ::: "memory");

    // ---- group 1: k chunks 16..31 ----
    #pragma unroll
    for (int it = 0; it < 8; it++) {
        const int i = it * NTHREADS + tid;
        const int row = i >> 4, u = (i & 15) + 16;
        cp_async16(lS_a + (uint32_t)(row * 512 + ((u ^ (row & 7)) << 4)),
                   &g_leftT[row * 32 + u]);
    }
    #pragma unroll
    for (int it = 0; it < 3; it++) {
        const int i = it * NTHREADS + tid;
        if (i < 640) {
            const int row = i >> 4, u = (i & 15) + 16;
            cp_async16(tS_a + (uint32_t)(row * 512 + ((u ^ (row & 7)) << 4)),
                       &g_tT[(size_t)(n0 + row) * 32 + u]);
        }
    }
    asm volatile("cp.async.commit_group;" ::: "memory");

    // ---- norms into registers (L2-hot; overlaps cp.async flight) ----
    const int m0  = wid * 16;
    const int g   = lane >> 2;
    const int tig = lane & 3;
    const int l7  = lane & 7;

    const int bgl = m0 + g;
    const float l0 = g_ln[bgl];
    const float l1 = g_ln[bgl + 8];
    float t0r[5], t1r[5];
    #pragma unroll
    for (int nb = 0; nb < 5; nb++) {
        const int col = nb * 8 + tig * 2;
        t0r[nb] = g_tn[n0 + col];
        t1r[nb] = g_tn[n0 + col + 1];
    }

    // ldmatrix lane bases
    const int hiA = lane >> 4;                         // 0/1: k-chunk select for A
    const int hiB = (lane >> 3) & 1;                   // 0/1: k-chunk select for B
    const uint32_t aBase = lS_a + (uint32_t)((m0 + (lane & 15)) * 512);
    uint32_t bBase[5];
    #pragma unroll
    for (int nb = 0; nb < 5; nb++)
        bBase[nb] = tS_a + (uint32_t)((nb * 8 + l7) * 512);

    float acc[5][4];
    #pragma unroll
    for (int nb = 0; nb < 5; nb++)
        #pragma unroll
        for (int c = 0; c < 4; c++) acc[nb][c] = 0.0f;

    // ---- first half: k-steps 0..7 (group 0 resident) ----
    asm volatile("cp.async.wait_group 1;" ::: "memory");
    __syncthreads();

    #pragma unroll
    for (int ks = 0; ks < 8; ks++) {
        uint32_t a0, a1, a2, a3;
        ldsm_x4(a0, a1, a2, a3, aBase + (uint32_t)((((2 * ks + hiA) ^ l7)) << 4));
        uint32_t bb[5][2];
        #pragma unroll
        for (int nb = 0; nb < 5; nb++)
            ldsm_x2(bb[nb][0], bb[nb][1],
                    bBase[nb] + (uint32_t)((((2 * ks + hiB) ^ l7)) << 4));
        #pragma unroll
        for (int nb = 0; nb < 5; nb++)
            mma_bf16(acc[nb], a0, a1, a2, a3, bb[nb][0], bb[nb][1]);
    }

    // ---- second half: k-steps 8..15 ----
    asm volatile("cp.async.wait_group 0;" ::: "memory");
    __syncthreads();

    #pragma unroll
    for (int ks = 8; ks < 16; ks++) {
        uint32_t a0, a1, a2, a3;
        ldsm_x4(a0, a1, a2, a3, aBase + (uint32_t)((((2 * ks + hiA) ^ l7)) << 4));
        uint32_t bb[5][2];
        #pragma unroll
        for (int nb = 0; nb < 5; nb++)
            ldsm_x2(bb[nb][0], bb[nb][1],
                    bBase[nb] + (uint32_t)((((2 * ks + hiB) ^ l7)) << 4));
        #pragma unroll
        for (int nb = 0; nb < 5; nb++)
            mma_bf16(acc[nb], a0, a1, a2, a3, bb[nb][0], bb[nb][1]);
    }

    // ---- epilogue: -sqrt(ln + tn - 2*dot) ----
    #pragma unroll
    for (int nb = 0; nb < 5; nb++) {
        const int n = n0 + nb * 8 + tig * 2;
        float v, sq;
        float2 w0, w1;
        v = fmaxf(l0 + t0r[nb] - 2.0f * acc[nb][0], 0.0f);
        asm("sqrt.approx.f32 %0, %1;" : "=f"(sq) : "f"(v));  w0.x = -sq;
        v = fmaxf(l0 + t1r[nb] - 2.0f * acc[nb][1], 0.0f);
        asm("sqrt.approx.f32 %0, %1;" : "=f"(sq) : "f"(v));  w0.y = -sq;
        v = fmaxf(l1 + t0r[nb] - 2.0f * acc[nb][2], 0.0f);
        asm("sqrt.approx.f32 %0, %1;" : "=f"(sq) : "f"(v));  w1.x = -sq;
        v = fmaxf(l1 + t1r[nb] - 2.0f * acc[nb][3], 0.0f);
        asm("sqrt.approx.f32 %0, %1;" : "=f"(sq) : "f"(v));  w1.y = -sq;

        *reinterpret_cast<float2*>(out + (size_t)bgl * NC + n)       = w0;
        *reinterpret_cast<float2*>(out + (size_t)(bgl + 8) * NC + n) = w1;
    }
}

// ---------------------------------------------------------------------------
extern "C" void kernel_launch(void* const* d_in, const int* in_sizes, int n_in,
                              void* d_out, int out_size) {
    const float* ent   = (const float*)d_in[0];
    const float* rel   = (const float*)d_in[1];
    const int*   heads = (const int*)d_in[2];
    const int*   rels  = (const int*)d_in[3];
    const int*   tails = (const int*)d_in[4];
    float* out = (float*)d_out;

    cudaFuncSetAttribute(score_kernel,
                         cudaFuncAttributeMaxDynamicSharedMemorySize, SMEM_DYN);

    pack_kernel<<<(NC + 31) / 32, 256>>>(ent, rel, heads, rels, tails);
    score_kernel<<<NBLK_S, NTHREADS, SMEM_DYN>>>(out);
}